// round 12
// baseline (speedup 1.0000x reference)
#include <cuda_runtime.h>
#include <math.h>

// Problem constants
#define BB    16
#define SS    2048
#define DD    768
#define HH    12
#define DKK   64
#define LL    307            // NUM_LOCAL = int((S-1)*0.15)

// ---------------------------------------------------------------------------
// Scratch (device globals — no allocation allowed in kernel_launch)
// ---------------------------------------------------------------------------
#define NLD  (BB * LL * DD)          // 3,772,416
#define NSD  (BB * SS * DD)          // 25,165,824
__device__ float g_scratch[3 * NLD + 2 * NSD];   // xlocal | q | ctx | k | v
__device__ int   g_topidx[BB * LL];

// ---------------------------------------------------------------------------
// f32x2 packed math (sm_103a FFMA2 — only reachable via PTX)
// ---------------------------------------------------------------------------
__device__ __forceinline__ unsigned long long pk2(float lo, float hi) {
    unsigned long long r;
    asm("mov.b64 %0, {%1, %2};" : "=l"(r) : "f"(lo), "f"(hi));
    return r;
}
__device__ __forceinline__ void fma2(unsigned long long& d,
                                     unsigned long long a,
                                     unsigned long long b) {
    asm("fma.rn.f32x2 %0, %1, %2, %0;" : "+l"(d) : "l"(a), "l"(b));
}
__device__ __forceinline__ float2 up2(unsigned long long v) {
    float2 r;
    asm("mov.b64 {%0, %1}, %2;" : "=f"(r.x), "=f"(r.y) : "l"(v));
    return r;
}

// ---------------------------------------------------------------------------
// Kernel 1: top-k via full bitonic sort of 2048 (value, index) pairs.
// Replicates jax.lax.top_k ordering: descending value, ascending index on ties.
// One block per batch.
// ---------------------------------------------------------------------------
__global__ void topk_kernel(const float* __restrict__ ar, int* __restrict__ topidx) {
    __shared__ float sv[2048];
    __shared__ int   si[2048];
    int b = blockIdx.x;
    const float* row = ar + (size_t)b * SS * SS + 1;   // ar[b, 0, 1:]
    for (int i = threadIdx.x; i < 2048; i += blockDim.x) {
        if (i < SS - 1) { sv[i] = row[i]; }
        else            { sv[i] = -INFINITY; }
        si[i] = i;
    }
    __syncthreads();
    for (int k = 2; k <= 2048; k <<= 1) {
        for (int j = k >> 1; j > 0; j >>= 1) {
            for (int t = threadIdx.x; t < 2048; t += blockDim.x) {
                int p = t ^ j;
                if (p > t) {
                    float v0 = sv[t], v1 = sv[p];
                    int   i0 = si[t], i1 = si[p];
                    // "before" == element at t should precede element at p
                    bool before = (v0 > v1) || (v0 == v1 && i0 < i1);
                    bool asc = ((t & k) == 0);
                    bool doswap = asc ? (!before) : before;
                    if (doswap) {
                        sv[t] = v1; sv[p] = v0;
                        si[t] = i1; si[p] = i0;
                    }
                }
            }
            __syncthreads();
        }
    }
    for (int r = threadIdx.x; r < LL; r += blockDim.x)
        topidx[b * LL + r] = si[r] + 1;
}

// ---------------------------------------------------------------------------
// Kernel 2: gather selected rows of x into xlocal. One block per (b, l) row.
// ---------------------------------------------------------------------------
__global__ void gather_kernel(const float* __restrict__ x,
                              const int* __restrict__ topidx,
                              float* __restrict__ xlocal) {
    int r = blockIdx.x;          // b*LL + l
    int b = r / LL;
    int src = topidx[r];
    const float4* xs = (const float4*)(x + ((size_t)b * SS + src) * DD);
    float4* xd = (float4*)(xlocal + (size_t)r * DD);
    xd[threadIdx.x] = xs[threadIdx.x];   // blockDim = 192 = 768/4
}

// ---------------------------------------------------------------------------
// Kernel 3: generic tiled SGEMM with f32x2 accumulation.
//   TB=true : C[m,n] = alpha * sum_k A[m,k] * B[n,k]   (B row-major N x K)
//   TB=false: C[m,n] = alpha * sum_k A[m,k] * B[k,n]   (B row-major K x N)
// Batched via blockIdx.z decomposed as (b, h) with separate strides.
// Requires K % BK == 0, float4-aligned pointers/lds (true for all our calls).
// ---------------------------------------------------------------------------
template<int BM, int BN, int BK, bool TB>
__global__ void __launch_bounds__((BM / 8) * (BN / 8))
gemm_kernel(const float* __restrict__ Ab, const float* __restrict__ Bb,
            float* __restrict__ Cb,
            int M, int N, int K, int lda, int ldb, int ldc,
            int nbh,
            long long sAb, long long sAh,
            long long sBb, long long sBh,
            long long sCb, long long sCh,
            float alpha) {
    constexpr int TW = BN / 8;
    constexpr int TH = BM / 8;
    constexpr int T  = TW * TH;
    __shared__ float As[BK][BM + 4];
    __shared__ float Bs[BK][BN + 4];

    int z  = blockIdx.z;
    int bb = z / nbh, hh = z % nbh;
    const float* A  = Ab + bb * sAb + hh * sAh;
    const float* Bp = Bb + bb * sBb + hh * sBh;
    float*       C  = Cb + bb * sCb + hh * sCh;

    int m0 = blockIdx.y * BM;
    int n0 = blockIdx.x * BN;
    int tid = threadIdx.x;
    int tn = tid % TW, tm = tid / TW;

    unsigned long long acc[8][4];
#pragma unroll
    for (int i = 0; i < 8; i++)
#pragma unroll
        for (int j = 0; j < 4; j++) acc[i][j] = 0ULL;

    for (int kt = 0; kt < K; kt += BK) {
        // A tile (BM x BK) -> As[k][m] (transposed scatter)
        for (int i = tid; i < BM * (BK / 4); i += T) {
            int row = i / (BK / 4);
            int kc  = (i % (BK / 4)) * 4;
            float4 v = make_float4(0.f, 0.f, 0.f, 0.f);
            int gm = m0 + row;
            if (gm < M) v = *(const float4*)(A + (size_t)gm * lda + kt + kc);
            As[kc + 0][row] = v.x; As[kc + 1][row] = v.y;
            As[kc + 2][row] = v.z; As[kc + 3][row] = v.w;
        }
        if (TB) {
            // B tile (BN x BK) -> Bs[k][n]
            for (int i = tid; i < BN * (BK / 4); i += T) {
                int row = i / (BK / 4);
                int kc  = (i % (BK / 4)) * 4;
                float4 v = make_float4(0.f, 0.f, 0.f, 0.f);
                int gn = n0 + row;
                if (gn < N) v = *(const float4*)(Bp + (size_t)gn * ldb + kt + kc);
                Bs[kc + 0][row] = v.x; Bs[kc + 1][row] = v.y;
                Bs[kc + 2][row] = v.z; Bs[kc + 3][row] = v.w;
            }
        } else {
            // B tile (BK x BN) -> Bs[k][n] (direct)
            for (int i = tid; i < BK * (BN / 4); i += T) {
                int kr = i / (BN / 4);
                int nc = (i % (BN / 4)) * 4;
                float4 v = make_float4(0.f, 0.f, 0.f, 0.f);
                int gn = n0 + nc;
                if (gn < N) v = *(const float4*)(Bp + (size_t)(kt + kr) * ldb + gn);
                *(float4*)&Bs[kr][nc] = v;
            }
        }
        __syncthreads();
#pragma unroll
        for (int kk = 0; kk < BK; kk++) {
            float4 a0 = *(const float4*)&As[kk][tm * 8];
            float4 a1 = *(const float4*)&As[kk][tm * 8 + 4];
            float4 b0 = *(const float4*)&Bs[kk][tn * 8];
            float4 b1 = *(const float4*)&Bs[kk][tn * 8 + 4];
            unsigned long long bp[4] = { pk2(b0.x, b0.y), pk2(b0.z, b0.w),
                                         pk2(b1.x, b1.y), pk2(b1.z, b1.w) };
            float av[8] = { a0.x, a0.y, a0.z, a0.w, a1.x, a1.y, a1.z, a1.w };
#pragma unroll
            for (int i = 0; i < 8; i++) {
                unsigned long long aa = pk2(av[i], av[i]);
#pragma unroll
                for (int j = 0; j < 4; j++) fma2(acc[i][j], aa, bp[j]);
            }
        }
        __syncthreads();
    }

#pragma unroll
    for (int i = 0; i < 8; i++) {
        int gm = m0 + tm * 8 + i;
        if (gm >= M) continue;
        float* crow = C + (size_t)gm * ldc + n0 + tn * 8;
#pragma unroll
        for (int j = 0; j < 4; j++) {
            float2 v = up2(acc[i][j]);
            int gn = n0 + tn * 8 + j * 2;
            if (gn + 1 < N) {
                crow[j * 2]     = alpha * v.x;
                crow[j * 2 + 1] = alpha * v.y;
            } else if (gn < N) {
                crow[j * 2] = alpha * v.x;
            }
        }
    }
}

// ---------------------------------------------------------------------------
// Kernel 4: row softmax, in place. One block (256 thr) per row of 2048.
// ---------------------------------------------------------------------------
__global__ void softmax_kernel(float* __restrict__ attn) {
    __shared__ float sh[8];
    float* row = attn + (size_t)blockIdx.x * SS;
    int tid = threadIdx.x;
    float4 v0 = *(float4*)(row + tid * 8);
    float4 v1 = *(float4*)(row + tid * 8 + 4);

    float m = fmaxf(fmaxf(fmaxf(v0.x, v0.y), fmaxf(v0.z, v0.w)),
                    fmaxf(fmaxf(v1.x, v1.y), fmaxf(v1.z, v1.w)));
#pragma unroll
    for (int o = 16; o; o >>= 1) m = fmaxf(m, __shfl_xor_sync(0xffffffffu, m, o));
    if ((tid & 31) == 0) sh[tid >> 5] = m;
    __syncthreads();
    m = sh[0];
#pragma unroll
    for (int w = 1; w < 8; w++) m = fmaxf(m, sh[w]);
    __syncthreads();

    float e0 = expf(v0.x - m), e1 = expf(v0.y - m), e2 = expf(v0.z - m), e3 = expf(v0.w - m);
    float e4 = expf(v1.x - m), e5 = expf(v1.y - m), e6 = expf(v1.z - m), e7 = expf(v1.w - m);
    float s = ((e0 + e1) + (e2 + e3)) + ((e4 + e5) + (e6 + e7));
#pragma unroll
    for (int o = 16; o; o >>= 1) s += __shfl_xor_sync(0xffffffffu, s, o);
    if ((tid & 31) == 0) sh[tid >> 5] = s;
    __syncthreads();
    s = 0.f;
#pragma unroll
    for (int w = 0; w < 8; w++) s += sh[w];
    float inv = 1.0f / s;

    v0.x = e0 * inv; v0.y = e1 * inv; v0.z = e2 * inv; v0.w = e3 * inv;
    v1.x = e4 * inv; v1.y = e5 * inv; v1.z = e6 * inv; v1.w = e7 * inv;
    *(float4*)(row + tid * 8)     = v0;
    *(float4*)(row + tid * 8 + 4) = v1;
}

// ---------------------------------------------------------------------------
// Launch
// ---------------------------------------------------------------------------
extern "C" void kernel_launch(void* const* d_in, const int* in_sizes, int n_in,
                              void* d_out, int out_size) {
    (void)in_sizes; (void)n_in; (void)out_size;
    const float* x  = (const float*)d_in[0];
    const float* ar = (const float*)d_in[1];
    const float* Wq = (const float*)d_in[2];
    const float* Wk = (const float*)d_in[3];
    const float* Wv = (const float*)d_in[4];
    const float* Wo = (const float*)d_in[5];

    float* out  = (float*)d_out;                        // (B, L, D)
    float* attn = out + (size_t)NLD;                    // (B, H, L, S)

    void* pscr = nullptr; void* ptop = nullptr;
    cudaGetSymbolAddress(&pscr, g_scratch);
    cudaGetSymbolAddress(&ptop, g_topidx);
    float* scratch = (float*)pscr;
    int*   topidx  = (int*)ptop;
    float* xlocal = scratch;
    float* qbuf   = scratch + (size_t)NLD;
    float* ctx    = scratch + (size_t)2 * NLD;
    float* kbuf   = scratch + (size_t)3 * NLD;
    float* vbuf   = kbuf + (size_t)NSD;

    const long long LD  = (long long)LL * DD;
    const long long SD  = (long long)SS * DD;
    const long long LS  = (long long)LL * SS;
    const long long HLS = (long long)HH * LS;

    // 1) top-k per batch
    topk_kernel<<<BB, 1024>>>(ar, topidx);

    // 2) gather x_local
    gather_kernel<<<BB * LL, DD / 4>>>(x, topidx, xlocal);

    // 3) projections: q = xlocal @ Wq^T ; k = x @ Wk^T ; v = x @ Wv^T
    {
        dim3 g(DD / 128, (BB * LL + 127) / 128, 1);
        gemm_kernel<128, 128, 16, true><<<g, 256>>>(
            xlocal, Wq, qbuf, BB * LL, DD, DD, DD, DD, DD,
            1, 0, 0, 0, 0, 0, 0, 1.0f);
    }
    {
        dim3 g(DD / 128, (BB * SS) / 128, 1);
        gemm_kernel<128, 128, 16, true><<<g, 256>>>(
            x, Wk, kbuf, BB * SS, DD, DD, DD, DD, DD,
            1, 0, 0, 0, 0, 0, 0, 1.0f);
        gemm_kernel<128, 128, 16, true><<<g, 256>>>(
            x, Wv, vbuf, BB * SS, DD, DD, DD, DD, DD,
            1, 0, 0, 0, 0, 0, 0, 1.0f);
    }

    // 4) scores[b,h,l,s] = (q . k) / 8  -> attention region of d_out
    {
        dim3 g(SS / 128, (LL + 127) / 128, BB * HH);
        gemm_kernel<128, 128, 16, true><<<g, 256>>>(
            qbuf, kbuf, attn, LL, SS, DKK, DD, DD, SS,
            HH, LD, 64, SD, 64, HLS, LS, 0.125f);
    }

    // 5) softmax rows (in place)
    softmax_kernel<<<BB * HH * LL, 256>>>(attn);

    // 6) context[b,l,h*64+dk] = attn @ v
    {
        dim3 g(1, (LL + 127) / 128, BB * HH);
        gemm_kernel<128, 64, 16, false><<<g, 128>>>(
            attn, vbuf, ctx, LL, DKK, SS, SS, DD, DD,
            HH, HLS, LS, SD, 64, LD, 64, 1.0f);
    }

    // 7) output = ctx @ Wo^T  -> first region of d_out
    {
        dim3 g(DD / 128, (BB * LL + 127) / 128, 1);
        gemm_kernel<128, 128, 16, true><<<g, 256>>>(
            ctx, Wo, out, BB * LL, DD, DD, DD, DD, DD,
            1, 0, 0, 0, 0, 0, 0, 1.0f);
    }
}